// round 9
// baseline (speedup 1.0000x reference)
#include <cuda_runtime.h>

// VLPLLoss: sampled Plackett-Luce counterfactual expected reward.
// Inputs (metadata order):
//   d_in[0] y_pred : float32 [B, D, 1]   B=4096, D=120
//   d_in[1] y_true : float32 [B, D, 1]
//   d_in[2] pO_slot: float32 [K]         K=10
//   d_in[3] gumbel : float32 [S, B, D]   S=128
// Output: float32 scalar = mean over (s,b) of sum_k pO[k] * y_true[b, topk_idx(s,b,k)]
//
// Strategy: one thread per (s,b) row. Block = 128 threads = all s for one b,
// so y_pred/y_true row lives in SMEM (keeps L2 traffic = gumbel stream only).
// Ordered top-10 via a branchless sorted-insertion chain on 32-bit keys:
//   key = bits(v + 32.0f) with low 7 mantissa bits replaced by (127 - d).
// All keys are positive floats -> uint order == float order, so FMNMX and
// IMNMX are interchangeable comparators (alternated to spread pipe pressure).
// Index embedded in the key => no payload to carry; labels gathered at the end.

#define B_DIM 4096
#define D_DIM 120
#define S_DIM 128
#define K_SLOTS 10
#define ROWS_TOTAL (B_DIM * S_DIM)

__device__ float g_partials[B_DIM];

__device__ __forceinline__ void step_f(unsigned& a, unsigned& k) {
    float fa = __uint_as_float(a), fk = __uint_as_float(k);
    float hi = fmaxf(fa, fk);
    float lo = fminf(fa, fk);
    a = __float_as_uint(hi);
    k = __float_as_uint(lo);
}
__device__ __forceinline__ void step_i(unsigned& a, unsigned& k) {
    unsigned hi = a > k ? a : k;
    unsigned lo = a > k ? k : a;
    a = hi;
    k = lo;
}

// Insert key K into sorted-descending a0..a9 (bubble pass, fully branchless).
#define INSERT10(K)                                         \
    do {                                                    \
        step_f(a0, K); step_i(a1, K); step_f(a2, K);        \
        step_i(a3, K); step_f(a4, K); step_i(a5, K);        \
        step_f(a6, K); step_i(a7, K); step_f(a8, K);        \
        step_i(a9, K);                                      \
    } while (0)

__global__ __launch_bounds__(S_DIM) void vlpl_topk_kernel(
    const float* __restrict__ y_pred,
    const float* __restrict__ y_true,
    const float* __restrict__ pO,
    const float* __restrict__ gumbel)
{
    __shared__ float yp_sh[D_DIM];   // y_pred row + 32.0f shift (all keys positive)
    __shared__ float yt_sh[D_DIM];   // y_true row
    __shared__ float po_sh[K_SLOTS];
    __shared__ float red[S_DIM];

    const int b = blockIdx.x;
    const int s = threadIdx.x;

    if (s < D_DIM) {
        yp_sh[s] = y_pred[b * D_DIM + s] + 32.0f;
        yt_sh[s] = y_true[b * D_DIM + s];
    }
    if (s < K_SLOTS) po_sh[s] = pO[s];
    __syncthreads();

    // gumbel row for (s, b): offset ((s*B + b) * D), 480 bytes, float4-aligned.
    const float4* __restrict__ g4 =
        reinterpret_cast<const float4*>(gumbel + ((size_t)s * B_DIM + b) * D_DIM);
    const float4* __restrict__ yp4 = reinterpret_cast<const float4*>(yp_sh);

    unsigned a0 = 0u, a1 = 0u, a2 = 0u, a3 = 0u, a4 = 0u;
    unsigned a5 = 0u, a6 = 0u, a7 = 0u, a8 = 0u, a9 = 0u;

#pragma unroll 6
    for (int c = 0; c < D_DIM / 4; ++c) {
        float4 g  = g4[c];
        float4 yp = yp4[c];
        unsigned lb = (unsigned)(127 - 4 * c);  // low bits for d = 4c (tie-break: smaller d wins)
        {
            float v = yp.x + g.x;
            unsigned k = (__float_as_uint(v) & 0xFFFFFF80u) | lb;
            INSERT10(k);
        }
        {
            float v = yp.y + g.y;
            unsigned k = (__float_as_uint(v) & 0xFFFFFF80u) | (lb - 1u);
            INSERT10(k);
        }
        {
            float v = yp.z + g.z;
            unsigned k = (__float_as_uint(v) & 0xFFFFFF80u) | (lb - 2u);
            INSERT10(k);
        }
        {
            float v = yp.w + g.w;
            unsigned k = (__float_as_uint(v) & 0xFFFFFF80u) | (lb - 3u);
            INSERT10(k);
        }
    }

    // Decode doc indices from low 7 bits; gather labels; weighted sum over slots.
    float reward;
    reward  = po_sh[0] * yt_sh[127 - (int)(a0 & 127u)];
    reward += po_sh[1] * yt_sh[127 - (int)(a1 & 127u)];
    reward += po_sh[2] * yt_sh[127 - (int)(a2 & 127u)];
    reward += po_sh[3] * yt_sh[127 - (int)(a3 & 127u)];
    reward += po_sh[4] * yt_sh[127 - (int)(a4 & 127u)];
    reward += po_sh[5] * yt_sh[127 - (int)(a5 & 127u)];
    reward += po_sh[6] * yt_sh[127 - (int)(a6 & 127u)];
    reward += po_sh[7] * yt_sh[127 - (int)(a7 & 127u)];
    reward += po_sh[8] * yt_sh[127 - (int)(a8 & 127u)];
    reward += po_sh[9] * yt_sh[127 - (int)(a9 & 127u)];

    // Deterministic block reduction -> per-b partial sum.
    red[s] = reward;
    __syncthreads();
#pragma unroll
    for (int off = S_DIM / 2; off > 0; off >>= 1) {
        if (s < off) red[s] += red[s + off];
        __syncthreads();
    }
    if (s == 0) g_partials[b] = red[0];
}

__global__ __launch_bounds__(1024) void vlpl_reduce_kernel(float* __restrict__ out)
{
    __shared__ double sm[1024];
    const int t = threadIdx.x;
    double acc = 0.0;
#pragma unroll
    for (int i = t; i < B_DIM; i += 1024) acc += (double)g_partials[i];
    sm[t] = acc;
    __syncthreads();
#pragma unroll
    for (int off = 512; off > 0; off >>= 1) {
        if (t < off) sm[t] += sm[t + off];
        __syncthreads();
    }
    if (t == 0) out[0] = (float)(sm[0] / (double)ROWS_TOTAL);
}

extern "C" void kernel_launch(void* const* d_in, const int* in_sizes, int n_in,
                              void* d_out, int out_size)
{
    const float* y_pred = (const float*)d_in[0];
    const float* y_true = (const float*)d_in[1];
    const float* pO     = (const float*)d_in[2];
    const float* gumbel = (const float*)d_in[3];
    float* out = (float*)d_out;

    vlpl_topk_kernel<<<B_DIM, S_DIM>>>(y_pred, y_true, pO, gumbel);
    vlpl_reduce_kernel<<<1, 1024>>>(out);
}

// round 10
// speedup vs baseline: 1.5060x; 1.5060x over previous
#include <cuda_runtime.h>

// VLPLLoss: sampled Plackett-Luce counterfactual expected reward.
//   d_in[0] y_pred : float32 [B, D, 1]   B=4096, D=120
//   d_in[1] y_true : float32 [B, D, 1]
//   d_in[2] pO_slot: float32 [K]         K=10
//   d_in[3] gumbel : float32 [S, B, D]   S=128
// out: scalar mean over (s,b) of sum_k pO[k] * y_true[b, topk_idx(s,b,k)]
//
// R9: sort16+bitonic-merge top-K (13 alu ops/elt vs 30 for insertion),
// smem-staged coalesced gumbel loads, fused fixed-point finalize (no 2nd kernel).
// Keys: bits(v+32.0f) with low 7 mantissa bits = (127 - doc); positive floats
// so uint order == float order; smaller doc wins ties (matches top_k).

#define B_DIM 4096
#define D_DIM 120
#define S_DIM 128
#define K_SLOTS 10
#define ROWS_TOTAL (B_DIM * S_DIM)
#define BD_STRIDE (B_DIM * D_DIM)

__device__ unsigned long long g_total = 0ull;
__device__ unsigned int g_count = 0u;

// compare-exchange: ensure x >= y (single IMNMX pair on sm_103a)
__device__ __forceinline__ void ce(unsigned& x, unsigned& y) {
    unsigned a = x, b = y;
    x = max(a, b);
    y = min(a, b);
}

// Batcher odd-even mergesort, n=16, descending (63 CEs)
__device__ __forceinline__ void sort16(unsigned* c) {
    ce(c[0],c[1]); ce(c[2],c[3]); ce(c[4],c[5]); ce(c[6],c[7]);
    ce(c[8],c[9]); ce(c[10],c[11]); ce(c[12],c[13]); ce(c[14],c[15]);
    ce(c[0],c[2]); ce(c[1],c[3]); ce(c[4],c[6]); ce(c[5],c[7]);
    ce(c[8],c[10]); ce(c[9],c[11]); ce(c[12],c[14]); ce(c[13],c[15]);
    ce(c[1],c[2]); ce(c[5],c[6]); ce(c[9],c[10]); ce(c[13],c[14]);
    ce(c[0],c[4]); ce(c[1],c[5]); ce(c[2],c[6]); ce(c[3],c[7]);
    ce(c[8],c[12]); ce(c[9],c[13]); ce(c[10],c[14]); ce(c[11],c[15]);
    ce(c[2],c[4]); ce(c[3],c[5]); ce(c[10],c[12]); ce(c[11],c[13]);
    ce(c[1],c[2]); ce(c[3],c[4]); ce(c[5],c[6]);
    ce(c[9],c[10]); ce(c[11],c[12]); ce(c[13],c[14]);
    ce(c[0],c[8]); ce(c[1],c[9]); ce(c[2],c[10]); ce(c[3],c[11]);
    ce(c[4],c[12]); ce(c[5],c[13]); ce(c[6],c[14]); ce(c[7],c[15]);
    ce(c[4],c[8]); ce(c[5],c[9]); ce(c[6],c[10]); ce(c[7],c[11]);
    ce(c[2],c[4]); ce(c[3],c[5]); ce(c[6],c[8]); ce(c[7],c[9]);
    ce(c[10],c[12]); ce(c[11],c[13]);
    ce(c[1],c[2]); ce(c[3],c[4]); ce(c[5],c[6]); ce(c[7],c[8]);
    ce(c[9],c[10]); ce(c[11],c[12]); ce(c[13],c[14]);
}

// Batcher sort n=8, descending (19 CEs)
__device__ __forceinline__ void sort8(unsigned* c) {
    ce(c[0],c[1]); ce(c[2],c[3]); ce(c[4],c[5]); ce(c[6],c[7]);
    ce(c[0],c[2]); ce(c[1],c[3]); ce(c[4],c[6]); ce(c[5],c[7]);
    ce(c[1],c[2]); ce(c[5],c[6]);
    ce(c[0],c[4]); ce(c[1],c[5]); ce(c[2],c[6]); ce(c[3],c[7]);
    ce(c[2],c[4]); ce(c[3],c[5]);
    ce(c[1],c[2]); ce(c[3],c[4]); ce(c[5],c[6]);
}

// bitonic cleanup of a bitonic 16-sequence -> fully sorted descending (32 CEs)
__device__ __forceinline__ void clean16(unsigned* L) {
    ce(L[0],L[8]); ce(L[1],L[9]); ce(L[2],L[10]); ce(L[3],L[11]);
    ce(L[4],L[12]); ce(L[5],L[13]); ce(L[6],L[14]); ce(L[7],L[15]);
    ce(L[0],L[4]); ce(L[1],L[5]); ce(L[2],L[6]); ce(L[3],L[7]);
    ce(L[8],L[12]); ce(L[9],L[13]); ce(L[10],L[14]); ce(L[11],L[15]);
    ce(L[0],L[2]); ce(L[1],L[3]); ce(L[4],L[6]); ce(L[5],L[7]);
    ce(L[8],L[10]); ce(L[9],L[11]); ce(L[12],L[14]); ce(L[13],L[15]);
    ce(L[0],L[1]); ce(L[2],L[3]); ce(L[4],L[5]); ce(L[6],L[7]);
    ce(L[8],L[9]); ce(L[10],L[11]); ce(L[12],L[13]); ce(L[14],L[15]);
}

__global__ __launch_bounds__(S_DIM) void vlpl_kernel(
    const float* __restrict__ y_pred,
    const float* __restrict__ y_true,
    const float* __restrict__ pO,
    const float* __restrict__ gumbel,
    float* __restrict__ out)
{
    __shared__ float yp_sh[D_DIM];
    __shared__ float yt_sh[D_DIM];
    __shared__ float po_sh[K_SLOTS];
    __shared__ float g_sh[S_DIM * 17];   // padded chunk buffer (conflict-free reads)
    __shared__ float wsum[4];

    const int b = blockIdx.x;
    const int t = threadIdx.x;

    if (t < D_DIM) {
        yp_sh[t] = y_pred[b * D_DIM + t] + 32.0f;
        yt_sh[t] = y_true[b * D_DIM + t];
    }
    if (t < K_SLOTS) po_sh[t] = pO[t];

    const size_t gb = (size_t)b * D_DIM;

    unsigned L[16];
#pragma unroll
    for (int i = 0; i < 16; ++i) L[i] = 0u;

    // ---- 7 chunks of 16 docs ----
    const int jf = (t & 3) * 4;   // float offset within a row-chunk for the loader
    const int r0 = t >> 2;        // base row this thread loads

#pragma unroll 1
    for (int c = 0; c < 7; ++c) {
        __syncthreads();   // previous chunk fully consumed
        // coalesced load: 128 rows x 64B; each thread 4x float4 (rows r0+32q)
#pragma unroll
        for (int q = 0; q < 4; ++q) {
            const int r = r0 + 32 * q;
            const float4 v = *reinterpret_cast<const float4*>(
                gumbel + (size_t)r * BD_STRIDE + gb + c * 16 + jf);
            float* dst = &g_sh[r * 17 + jf];
            dst[0] = v.x; dst[1] = v.y; dst[2] = v.z; dst[3] = v.w;
        }
        __syncthreads();

        unsigned C[16];
        const int dbase = c * 16;
#pragma unroll
        for (int i = 0; i < 16; ++i) {
            const float v = yp_sh[dbase + i] + g_sh[t * 17 + i];
            C[i] = (__float_as_uint(v) & 0xFFFFFF80u) | (unsigned)(127 - dbase - i);
        }
        sort16(C);
        // bitonic merge: keep top-16 of (L desc) U (C desc)
#pragma unroll
        for (int i = 0; i < 16; ++i) L[i] = max(L[i], C[15 - i]);
        clean16(L);
    }

    // ---- remainder: docs 112..119 (chunk of 8, zero-padded merge) ----
    {
        __syncthreads();
        const int jf8 = (t & 1) * 4;
        const int r08 = t >> 1;
#pragma unroll
        for (int q = 0; q < 2; ++q) {
            const int r = r08 + 64 * q;
            const float4 v = *reinterpret_cast<const float4*>(
                gumbel + (size_t)r * BD_STRIDE + gb + 112 + jf8);
            float* dst = &g_sh[r * 9 + jf8];
            dst[0] = v.x; dst[1] = v.y; dst[2] = v.z; dst[3] = v.w;
        }
        __syncthreads();

        unsigned C[8];
#pragma unroll
        for (int i = 0; i < 8; ++i) {
            const float v = yp_sh[112 + i] + g_sh[t * 9 + i];
            C[i] = (__float_as_uint(v) & 0xFFFFFF80u) | (unsigned)(15 - i);
        }
        sort8(C);
        // padded C[8..15] = 0  =>  L[0..7] unchanged, L[8..15] merge with C[15-i]
#pragma unroll
        for (int i = 8; i < 16; ++i) L[i] = max(L[i], C[15 - i]);
        clean16(L);
    }

    // ---- decode top-10, gather labels, weighted sum ----
    float reward = 0.0f;
#pragma unroll
    for (int k = 0; k < K_SLOTS; ++k)
        reward += po_sh[k] * yt_sh[127 - (int)(L[k] & 127u)];

    // ---- deterministic reduction: warp shuffle + fixed-point global atomic ----
#pragma unroll
    for (int off = 16; off > 0; off >>= 1)
        reward += __shfl_down_sync(0xFFFFFFFFu, reward, off);
    if ((t & 31) == 0) wsum[t >> 5] = reward;
    __syncthreads();

    if (t == 0) {
        const float part = (wsum[0] + wsum[1]) + (wsum[2] + wsum[3]);
        // rewards are nonnegative; block partial <= 1280 -> fits with 2^32 scale
        const unsigned long long fx =
            (unsigned long long)((double)part * 4294967296.0);
        atomicAdd(&g_total, fx);
        __threadfence();
        const unsigned prev = atomicAdd(&g_count, 1u);
        if (prev == (unsigned)(B_DIM - 1)) {
            // last block: all g_total adds are visible (fence-before-count)
            const unsigned long long tot = atomicExch(&g_total, 0ull);
            out[0] = (float)((double)tot * (1.0 / 4294967296.0)
                             / (double)ROWS_TOTAL);
            atomicExch(&g_count, 0u);   // reset for next graph replay
        }
    }
}

extern "C" void kernel_launch(void* const* d_in, const int* in_sizes, int n_in,
                              void* d_out, int out_size)
{
    const float* y_pred = (const float*)d_in[0];
    const float* y_true = (const float*)d_in[1];
    const float* pO     = (const float*)d_in[2];
    const float* gumbel = (const float*)d_in[3];
    float* out = (float*)d_out;

    vlpl_kernel<<<B_DIM, S_DIM>>>(y_pred, y_true, pO, gumbel, out);
}

// round 11
// speedup vs baseline: 1.6241x; 1.0785x over previous
#include <cuda_runtime.h>

// VLPLLoss: sampled Plackett-Luce counterfactual expected reward.
//   d_in[0] y_pred : float32 [B, D, 1]   B=4096, D=120
//   d_in[1] y_true : float32 [B, D, 1]
//   d_in[2] pO_slot: float32 [K]         K=10
//   d_in[3] gumbel : float32 [S, B, D]   S=128
// out: scalar mean over (s,b) of sum_k pO[k] * y_true[b, topk_idx(s,b,k)]
//
// R11: top-10 lists everywhere.
//  - chunk(16): pruned Batcher network -> sorted top-10 (60 CE)
//  - merge sorted-10 lists: m[i]=max(L[i],C[9-i]) (10 max) + clean10 (15 CE)
//  - y_pred folded into the smem loader; double-buffered chunks, 1 barrier/chunk
// Keys: bits(v) with low 7 mantissa bits = (127 - doc), v = y_pred+gumbel+32 > 0
// -> uint order == float order, keys distinct, smaller doc wins ties (== top_k).

#define B_DIM 4096
#define D_DIM 120
#define S_DIM 128
#define K_SLOTS 10
#define ROWS_TOTAL (B_DIM * S_DIM)
#define BD_STRIDE (B_DIM * D_DIM)
#define STR 17   // smem row stride (odd -> conflict-free scalar access)

__device__ unsigned long long g_total = 0ull;
__device__ unsigned int g_count = 0u;

// compare-exchange: ensure x >= y (IMNMX pair)
__device__ __forceinline__ void ce(unsigned& x, unsigned& y) {
    unsigned a = x, b = y;
    x = max(a, b);
    y = min(a, b);
}

// Batcher sort16 pruned to outputs 0..9: positions 0..9 = sorted-desc top-10.
// (full sort16 minus ce(11,13) and final-stage ce(11,12), ce(13,14))
__device__ __forceinline__ void top10of16(unsigned* c) {
    ce(c[0],c[1]); ce(c[2],c[3]); ce(c[4],c[5]); ce(c[6],c[7]);
    ce(c[8],c[9]); ce(c[10],c[11]); ce(c[12],c[13]); ce(c[14],c[15]);
    ce(c[0],c[2]); ce(c[1],c[3]); ce(c[4],c[6]); ce(c[5],c[7]);
    ce(c[8],c[10]); ce(c[9],c[11]); ce(c[12],c[14]); ce(c[13],c[15]);
    ce(c[1],c[2]); ce(c[5],c[6]); ce(c[9],c[10]); ce(c[13],c[14]);
    ce(c[0],c[4]); ce(c[1],c[5]); ce(c[2],c[6]); ce(c[3],c[7]);
    ce(c[8],c[12]); ce(c[9],c[13]); ce(c[10],c[14]); ce(c[11],c[15]);
    ce(c[2],c[4]); ce(c[3],c[5]); ce(c[10],c[12]); ce(c[11],c[13]);
    ce(c[1],c[2]); ce(c[3],c[4]); ce(c[5],c[6]);
    ce(c[9],c[10]); ce(c[11],c[12]); ce(c[13],c[14]);
    ce(c[0],c[8]); ce(c[1],c[9]); ce(c[2],c[10]); ce(c[3],c[11]);
    ce(c[4],c[12]); ce(c[5],c[13]); ce(c[6],c[14]); ce(c[7],c[15]);
    ce(c[4],c[8]); ce(c[5],c[9]); ce(c[6],c[10]); ce(c[7],c[11]);
    ce(c[2],c[4]); ce(c[3],c[5]); ce(c[6],c[8]); ce(c[7],c[9]); ce(c[10],c[12]);
    ce(c[1],c[2]); ce(c[3],c[4]); ce(c[5],c[6]); ce(c[7],c[8]); ce(c[9],c[10]);
}

// Batcher sort8 descending (19 CE)
__device__ __forceinline__ void sort8(unsigned* c) {
    ce(c[0],c[1]); ce(c[2],c[3]); ce(c[4],c[5]); ce(c[6],c[7]);
    ce(c[0],c[2]); ce(c[1],c[3]); ce(c[4],c[6]); ce(c[5],c[7]);
    ce(c[1],c[2]); ce(c[5],c[6]);
    ce(c[0],c[4]); ce(c[1],c[5]); ce(c[2],c[6]); ce(c[3],c[7]);
    ce(c[2],c[4]); ce(c[3],c[5]);
    ce(c[1],c[2]); ce(c[3],c[4]); ce(c[5],c[6]);
}

// Knuth bitonic cleanup for length-10 (desc-then-asc) sequence -> sorted desc (15 CE)
__device__ __forceinline__ void clean10(unsigned* m) {
    ce(m[0],m[8]); ce(m[1],m[9]);
    ce(m[0],m[4]); ce(m[1],m[5]); ce(m[2],m[6]); ce(m[3],m[7]);
    ce(m[0],m[2]); ce(m[1],m[3]); ce(m[4],m[6]); ce(m[5],m[7]);
    ce(m[0],m[1]); ce(m[2],m[3]); ce(m[4],m[5]); ce(m[6],m[7]);
    ce(m[8],m[9]);
}

__global__ __launch_bounds__(S_DIM) void vlpl_kernel(
    const float* __restrict__ y_pred,
    const float* __restrict__ y_true,
    const float* __restrict__ pO,
    const float* __restrict__ gumbel,
    float* __restrict__ out)
{
    __shared__ float yp_sh[D_DIM];
    __shared__ float yt_sh[D_DIM];
    __shared__ float po_sh[K_SLOTS];
    __shared__ float g_sh[2][S_DIM * STR];   // double-buffered chunk staging
    __shared__ float wsum[4];

    const int b = blockIdx.x;
    const int t = threadIdx.x;

    if (t < D_DIM) {
        yp_sh[t] = y_pred[b * D_DIM + t] + 32.0f;
        yt_sh[t] = y_true[b * D_DIM + t];
    }
    if (t < K_SLOTS) po_sh[t] = pO[t];
    __syncthreads();   // yp_sh used by the loader below

    const size_t gb = (size_t)b * D_DIM;
    const int jf = (t & 3) * 4;    // float offset within a 16-doc chunk row
    const int r0 = t >> 2;         // base row for the loader
    const float* __restrict__ gbase = gumbel + gb + (size_t)r0 * BD_STRIDE + jf;

    // ---- preload chunk 0 into buffer 0 (yp folded in at load time) ----
    {
        const float4 yp4 = *reinterpret_cast<const float4*>(&yp_sh[jf]);
#pragma unroll
        for (int q = 0; q < 4; ++q) {
            const float4 v = *reinterpret_cast<const float4*>(
                gbase + (size_t)q * 32 * BD_STRIDE);
            float* dst = &g_sh[0][(r0 + 32 * q) * STR + jf];
            dst[0] = v.x + yp4.x; dst[1] = v.y + yp4.y;
            dst[2] = v.z + yp4.z; dst[3] = v.w + yp4.w;
        }
    }
    __syncthreads();

    unsigned L[10];
#pragma unroll
    for (int i = 0; i < 10; ++i) L[i] = 0u;

#pragma unroll
    for (int c = 0; c < 7; ++c) {
        // ---- issue loads for the next chunk (or remainder) ----
        if (c < 6) {
            const float4 yp4 =
                *reinterpret_cast<const float4*>(&yp_sh[(c + 1) * 16 + jf]);
#pragma unroll
            for (int q = 0; q < 4; ++q) {
                const float4 v = *reinterpret_cast<const float4*>(
                    gbase + (size_t)q * 32 * BD_STRIDE + (c + 1) * 16);
                float* dst = &g_sh[(c + 1) & 1][(r0 + 32 * q) * STR + jf];
                dst[0] = v.x + yp4.x; dst[1] = v.y + yp4.y;
                dst[2] = v.z + yp4.z; dst[3] = v.w + yp4.w;
            }
        } else {
            // remainder (docs 112..119) into buffer 1
            const int jf8 = (t & 1) * 4;
            const int r8 = t >> 1;
            const float4 yp4 = *reinterpret_cast<const float4*>(&yp_sh[112 + jf8]);
            const float* __restrict__ gb8 =
                gumbel + gb + (size_t)r8 * BD_STRIDE + 112 + jf8;
#pragma unroll
            for (int q = 0; q < 2; ++q) {
                const float4 v = *reinterpret_cast<const float4*>(
                    gb8 + (size_t)q * 64 * BD_STRIDE);
                float* dst = &g_sh[1][(r8 + 64 * q) * STR + jf8];
                dst[0] = v.x + yp4.x; dst[1] = v.y + yp4.y;
                dst[2] = v.z + yp4.z; dst[3] = v.w + yp4.w;
            }
        }

        // ---- compute chunk c from buffer c&1 ----
        unsigned C[16];
#pragma unroll
        for (int i = 0; i < 16; ++i) {
            const float v = g_sh[c & 1][t * STR + i];
            C[i] = (__float_as_uint(v) & 0xFFFFFF80u)
                 | (unsigned)(127 - c * 16 - i);
        }
        top10of16(C);
        // equal-length-10 merge: pairs (L[i], C[9-i]) each hold exactly one
        // member of the union's top-10 (keys distinct) -> max picks it.
#pragma unroll
        for (int i = 0; i < 10; ++i) L[i] = max(L[i], C[9 - i]);
        clean10(L);
        __syncthreads();
    }

    // ---- remainder compute: 8 docs from buffer 1, zero-padded merge ----
    {
        unsigned C[8];
#pragma unroll
        for (int i = 0; i < 8; ++i) {
            const float v = g_sh[1][t * STR + i];
            C[i] = (__float_as_uint(v) & 0xFFFFFF80u) | (unsigned)(15 - i);
        }
        sort8(C);
        // pad C[8]=C[9]=0 => positions 0,1 of L untouched
#pragma unroll
        for (int i = 2; i < 10; ++i) L[i] = max(L[i], C[9 - i]);
        clean10(L);
    }

    // ---- decode top-10, gather labels, weighted sum ----
    float reward = 0.0f;
#pragma unroll
    for (int k = 0; k < K_SLOTS; ++k)
        reward += po_sh[k] * yt_sh[127 - (int)(L[k] & 127u)];

    // ---- deterministic reduction: warp shuffle + fixed-point global atomic ----
#pragma unroll
    for (int off = 16; off > 0; off >>= 1)
        reward += __shfl_down_sync(0xFFFFFFFFu, reward, off);
    if ((t & 31) == 0) wsum[t >> 5] = reward;
    __syncthreads();

    if (t == 0) {
        const float part = (wsum[0] + wsum[1]) + (wsum[2] + wsum[3]);
        // rewards nonnegative; block partial <= 1280 -> fits with 2^32 scale
        const unsigned long long fx =
            (unsigned long long)((double)part * 4294967296.0);
        atomicAdd(&g_total, fx);
        __threadfence();
        const unsigned prev = atomicAdd(&g_count, 1u);
        if (prev == (unsigned)(B_DIM - 1)) {
            const unsigned long long tot = atomicExch(&g_total, 0ull);
            out[0] = (float)((double)tot * (1.0 / 4294967296.0)
                             / (double)ROWS_TOTAL);
            atomicExch(&g_count, 0u);   // reset for next graph replay
        }
    }
}

extern "C" void kernel_launch(void* const* d_in, const int* in_sizes, int n_in,
                              void* d_out, int out_size)
{
    const float* y_pred = (const float*)d_in[0];
    const float* y_true = (const float*)d_in[1];
    const float* pO     = (const float*)d_in[2];
    const float* gumbel = (const float*)d_in[3];
    float* out = (float*)d_out;

    vlpl_kernel<<<B_DIM, S_DIM>>>(y_pred, y_true, pO, gumbel, out);
}